// round 1
// baseline (speedup 1.0000x reference)
#include <cuda_runtime.h>
#include <math.h>

#define N_TOK   4096
#define E_DIM   1024
#define H_DIM   2730
#define HPAD    2816          // 22 * 128
#define NEXP    8
#define NPAIR   8192          // N_TOK * TOP_K
#define BM      64
#define BN      128
#define BK      16

// ---------------- device scratch (allocation-free: static globals) ----------
__device__ int   g_cnt[NEXP];
__device__ int   g_off[NEXP + 1];
__device__ int   g_cur[NEXP];
__device__ int   g_te[N_TOK * 2];
__device__ float g_tw[N_TOK * 2];
__device__ int   g_tok[NPAIR];
__device__ float g_wt[NPAIR];
__device__ __align__(16) float g_h[(size_t)NPAIR * HPAD];       // ~88 MB
__device__ __align__(16) float g_acc[(size_t)N_TOK * E_DIM];    // ~16 MB

// ---------------- init: zero counters, accumulator = x (residual) -----------
__global__ void k_init(const float* __restrict__ x) {
    int i = blockIdx.x * blockDim.x + threadIdx.x;
    if (i < NEXP) g_cnt[i] = 0;
    // 4096 blocks * 256 threads = exactly N_TOK*E_DIM/4 float4s
    ((float4*)g_acc)[i] = ((const float4*)x)[i];
}

// ---------------- router: 1 warp per token ----------------------------------
__global__ void k_router(const float* __restrict__ x, const float* __restrict__ Wr) {
    int warp = (blockIdx.x * blockDim.x + threadIdx.x) >> 5;
    int lane = threadIdx.x & 31;
    if (warp >= N_TOK) return;
    const float* xr = x + (size_t)warp * E_DIM;

    float acc[NEXP];
#pragma unroll
    for (int c = 0; c < NEXP; c++) acc[c] = 0.f;

    for (int k = lane; k < E_DIM; k += 32) {
        float xv = xr[k];
#pragma unroll
        for (int c = 0; c < NEXP; c++) acc[c] += xv * Wr[c * E_DIM + k];
    }
#pragma unroll
    for (int c = 0; c < NEXP; c++) {
#pragma unroll
        for (int o = 16; o > 0; o >>= 1)
            acc[c] += __shfl_xor_sync(0xffffffffu, acc[c], o);
    }
    if (lane == 0) {
        // top-2 (strict > keeps lower index on ties, matching lax.top_k)
        int b0 = 0; float v0 = acc[0];
#pragma unroll
        for (int c = 1; c < NEXP; c++) if (acc[c] > v0) { v0 = acc[c]; b0 = c; }
        int b1 = -1; float v1 = -3.4e38f;
#pragma unroll
        for (int c = 0; c < NEXP; c++) if (c != b0 && acc[c] > v1) { v1 = acc[c]; b1 = c; }
        float t  = expf(v1 - v0);           // v1 <= v0, t in (0,1]
        float w0 = 1.f / (1.f + t);
        float w1 = t * w0;
        g_te[warp * 2 + 0] = b0; g_tw[warp * 2 + 0] = w0;
        g_te[warp * 2 + 1] = b1; g_tw[warp * 2 + 1] = w1;
        atomicAdd(&g_cnt[b0], 1);
        atomicAdd(&g_cnt[b1], 1);
    }
}

// ---------------- prefix sum over 8 experts ----------------------------------
__global__ void k_prefix() {
    if (threadIdx.x == 0 && blockIdx.x == 0) {
        int s = 0;
        for (int c = 0; c < NEXP; c++) { g_off[c] = s; g_cur[c] = s; s += g_cnt[c]; }
        g_off[NEXP] = s;
    }
}

// ---------------- scatter tokens into packed per-expert lists ----------------
__global__ void k_scatter() {
    int n = blockIdx.x * blockDim.x + threadIdx.x;
    if (n >= N_TOK) return;
#pragma unroll
    for (int k = 0; k < 2; k++) {
        int e = g_te[n * 2 + k];
        int slot = atomicAdd(&g_cur[e], 1);
        g_tok[slot] = n;
        g_wt[slot]  = g_tw[n * 2 + k];
    }
}

// ---------------- GEMM1: h = silu(X@Wv + bv) * (X@Wg + bg) -------------------
// grid: (HPAD/BN=22, 64, NEXP), block: 256
__global__ void __launch_bounds__(256) k_gemm1(
    const float* __restrict__ x,
    const float* __restrict__ Wv, const float* __restrict__ bv,
    const float* __restrict__ Wg, const float* __restrict__ bg)
{
    int e     = blockIdx.z;
    int rbase = g_off[e] + blockIdx.y * BM;
    int rend  = g_off[e + 1];
    if (rbase >= rend) return;
    int cbase = blockIdx.x * BN;

    __shared__ float sA[BK][BM + 1];
    __shared__ __align__(16) float sBv[BK][BN];
    __shared__ __align__(16) float sBg[BK][BN];
    __shared__ int stok[BM];

    int tid = threadIdx.x;
    if (tid < BM) {
        int slot = rbase + tid;
        stok[tid] = (slot < rend) ? g_tok[slot] : 0;
    }
    __syncthreads();

    int tx = tid & 15, ty = tid >> 4;
    float accv[4][8], accg[4][8];
#pragma unroll
    for (int i = 0; i < 4; i++)
#pragma unroll
        for (int j = 0; j < 8; j++) { accv[i][j] = 0.f; accg[i][j] = 0.f; }

    const float* Wvp = Wv + (size_t)e * E_DIM * H_DIM + cbase;
    const float* Wgp = Wg + (size_t)e * E_DIM * H_DIM + cbase;

    for (int kb = 0; kb < E_DIM; kb += BK) {
        // A: 64x16 gathered rows of x, stored transposed
#pragma unroll
        for (int i = 0; i < 4; i++) {
            int idx = tid + i * 256;
            int m = idx >> 4, k = idx & 15;
            sA[k][m] = x[(size_t)stok[m] * E_DIM + kb + k];
        }
        // B: 16x128 of Wv and Wg (bounds-guarded on H)
#pragma unroll
        for (int i = 0; i < 8; i++) {
            int idx = tid + i * 256;
            int k = idx >> 7, j = idx & 127;
            int gc = cbase + j;
            float vv = 0.f, gg = 0.f;
            if (gc < H_DIM) {
                size_t o = (size_t)(kb + k) * H_DIM + j;
                vv = Wvp[o];
                gg = Wgp[o];
            }
            sBv[k][j] = vv; sBg[k][j] = gg;
        }
        __syncthreads();

#pragma unroll
        for (int kk = 0; kk < BK; kk++) {
            float aa[4];
#pragma unroll
            for (int i = 0; i < 4; i++) aa[i] = sA[kk][ty * 4 + i];
            float4 v0 = *(const float4*)&sBv[kk][tx * 4];
            float4 v1 = *(const float4*)&sBv[kk][64 + tx * 4];
            float4 q0 = *(const float4*)&sBg[kk][tx * 4];
            float4 q1 = *(const float4*)&sBg[kk][64 + tx * 4];
            float bvv[8] = {v0.x, v0.y, v0.z, v0.w, v1.x, v1.y, v1.z, v1.w};
            float bgg[8] = {q0.x, q0.y, q0.z, q0.w, q1.x, q1.y, q1.z, q1.w};
#pragma unroll
            for (int i = 0; i < 4; i++)
#pragma unroll
                for (int j = 0; j < 8; j++) {
                    accv[i][j] += aa[i] * bvv[j];
                    accg[i][j] += aa[i] * bgg[j];
                }
        }
        __syncthreads();
    }

    // SwiGLU epilogue -> g_h (pad columns written as 0)
#pragma unroll
    for (int i = 0; i < 4; i++) {
        int slot = rbase + ty * 4 + i;
        if (slot >= rend) continue;
        float* hrow = g_h + (size_t)slot * HPAD + cbase;
#pragma unroll
        for (int j = 0; j < 8; j++) {
            int lc = (j < 4) ? (tx * 4 + j) : (64 + tx * 4 + j - 4);
            int gc = cbase + lc;
            float outv = 0.f;
            if (gc < H_DIM) {
                float vv = accv[i][j] + bv[e * H_DIM + gc];
                float gg = accg[i][j] + bg[e * H_DIM + gc];
                outv = vv / (1.f + expf(-vv)) * gg;   // silu(vv) * gg
            }
            hrow[lc] = outv;
        }
    }
}

// ---------------- GEMM2: out += w * (h @ Wo + bo) into g_acc -----------------
// grid: (E_DIM/BN=8, 64, NEXP), block: 256
__global__ void __launch_bounds__(256) k_gemm2(
    const float* __restrict__ Wo, const float* __restrict__ bo)
{
    int e     = blockIdx.z;
    int rbase = g_off[e] + blockIdx.y * BM;
    int rend  = g_off[e + 1];
    if (rbase >= rend) return;
    int cbase = blockIdx.x * BN;

    __shared__ float sA[BK][BM + 1];
    __shared__ __align__(16) float sB[BK][BN];

    int tid = threadIdx.x;
    int tx = tid & 15, ty = tid >> 4;
    float acc[4][8];
#pragma unroll
    for (int i = 0; i < 4; i++)
#pragma unroll
        for (int j = 0; j < 8; j++) acc[i][j] = 0.f;

    const float* Wop = Wo + (size_t)e * H_DIM * E_DIM + cbase;

    for (int kb = 0; kb < HPAD; kb += BK) {
#pragma unroll
        for (int i = 0; i < 4; i++) {
            int idx = tid + i * 256;
            int m = idx >> 4, k = idx & 15;
            int slot = rbase + m;
            sA[k][m] = (slot < rend) ? g_h[(size_t)slot * HPAD + kb + k] : 0.f;
        }
#pragma unroll
        for (int i = 0; i < 8; i++) {
            int idx = tid + i * 256;
            int k = idx >> 7, j = idx & 127;
            int gk = kb + k;
            sB[k][j] = (gk < H_DIM) ? Wop[(size_t)gk * E_DIM + j] : 0.f;
        }
        __syncthreads();

#pragma unroll
        for (int kk = 0; kk < BK; kk++) {
            float aa[4];
#pragma unroll
            for (int i = 0; i < 4; i++) aa[i] = sA[kk][ty * 4 + i];
            float4 b0 = *(const float4*)&sB[kk][tx * 4];
            float4 b1 = *(const float4*)&sB[kk][64 + tx * 4];
            float bb[8] = {b0.x, b0.y, b0.z, b0.w, b1.x, b1.y, b1.z, b1.w};
#pragma unroll
            for (int i = 0; i < 4; i++)
#pragma unroll
                for (int j = 0; j < 8; j++)
                    acc[i][j] += aa[i] * bb[j];
        }
        __syncthreads();
    }

#pragma unroll
    for (int i = 0; i < 4; i++) {
        int slot = rbase + ty * 4 + i;
        if (slot >= rend) continue;
        int   tok = g_tok[slot];
        float w   = g_wt[slot];
        const float* bop = bo + e * E_DIM + cbase;
        float* dst = g_acc + (size_t)tok * E_DIM + cbase;
#pragma unroll
        for (int j = 0; j < 8; j++) {
            int lc = (j < 4) ? (tx * 4 + j) : (64 + tx * 4 + j - 4);
            atomicAdd(&dst[lc], w * (acc[i][j] + bop[lc]));
        }
    }
}

// ---------------- LayerNorm ---------------------------------------------------
__global__ void k_ln(const float* __restrict__ lng, const float* __restrict__ lnb,
                     float* __restrict__ out)
{
    int n   = blockIdx.x;
    int tid = threadIdx.x;   // 256
    const float4* row = (const float4*)(g_acc + (size_t)n * E_DIM);
    float4 v = row[tid];
    float s  = v.x + v.y + v.z + v.w;
    float ss = v.x * v.x + v.y * v.y + v.z * v.z + v.w * v.w;
#pragma unroll
    for (int o = 16; o > 0; o >>= 1) {
        s  += __shfl_xor_sync(0xffffffffu, s,  o);
        ss += __shfl_xor_sync(0xffffffffu, ss, o);
    }
    __shared__ float sred[16];
    int w = tid >> 5, l = tid & 31;
    if (l == 0) { sred[w] = s; sred[8 + w] = ss; }
    __syncthreads();
    if (tid < 32) {
        float a = (tid < 8) ? sred[tid]     : 0.f;
        float c = (tid < 8) ? sred[8 + tid] : 0.f;
#pragma unroll
        for (int o = 4; o > 0; o >>= 1) {
            a += __shfl_xor_sync(0xffffffffu, a, o);
            c += __shfl_xor_sync(0xffffffffu, c, o);
        }
        if (tid == 0) { sred[0] = a; sred[1] = c; }
    }
    __syncthreads();
    float mu  = sred[0] * (1.f / E_DIM);
    float var = sred[1] * (1.f / E_DIM) - mu * mu;
    float inv = rsqrtf(var + 1e-5f);
    float4 g4 = ((const float4*)lng)[tid];
    float4 b4 = ((const float4*)lnb)[tid];
    float4 o4;
    o4.x = (v.x - mu) * inv * g4.x + b4.x;
    o4.y = (v.y - mu) * inv * g4.y + b4.y;
    o4.z = (v.z - mu) * inv * g4.z + b4.z;
    o4.w = (v.w - mu) * inv * g4.w + b4.w;
    ((float4*)out)[(size_t)n * (E_DIM / 4) + tid] = o4;
}

// ---------------- launcher ----------------------------------------------------
extern "C" void kernel_launch(void* const* d_in, const int* in_sizes, int n_in,
                              void* d_out, int out_size)
{
    const float* x   = (const float*)d_in[0];
    const float* Wr  = (const float*)d_in[1];
    const float* Wv  = (const float*)d_in[2];
    const float* bv  = (const float*)d_in[3];
    const float* Wg  = (const float*)d_in[4];
    const float* bg  = (const float*)d_in[5];
    const float* Wo  = (const float*)d_in[6];
    const float* bo  = (const float*)d_in[7];
    const float* lng = (const float*)d_in[8];
    const float* lnb = (const float*)d_in[9];
    float* out = (float*)d_out;

    k_init<<<(N_TOK * E_DIM / 4) / 256, 256>>>(x);
    k_router<<<(N_TOK * 32) / 256, 256>>>(x, Wr);
    k_prefix<<<1, 32>>>();
    k_scatter<<<N_TOK / 256, 256>>>();

    dim3 g1(HPAD / BN, N_TOK / BM, NEXP);   // (22, 64, 8)
    k_gemm1<<<g1, 256>>>(x, Wv, bv, Wg, bg);

    dim3 g2(E_DIM / BN, N_TOK / BM, NEXP);  // (8, 64, 8)
    k_gemm2<<<g2, 256>>>(Wo, bo);

    k_ln<<<N_TOK, 256>>>(lng, lnb, out);
}

// round 4
// speedup vs baseline: 1.2239x; 1.2239x over previous
#include <cuda_runtime.h>
#include <math.h>
#include <stdint.h>

#define N_TOK 4096
#define E_DIM 1024
#define H_DIM 2730
#define HPAD  2816
#define KPAD  2752          // 43*64, GEMM2 k extent (g_h zero-padded to here)
#define NEXP  8
#define NPAIR 8192
#define MAXT  136           // max 64-row tiles: 8192/64 + 7

// ---------------- device scratch ----------------
__device__ int   g_cnt[NEXP];
__device__ int   g_off[NEXP + 1];
__device__ int   g_cur[NEXP];
__device__ int   g_te[N_TOK * 2];
__device__ float g_tw[N_TOK * 2];
__device__ int   g_tok[NPAIR];
__device__ float g_wt[NPAIR];
__device__ int   g_tile_e[MAXT];
__device__ int   g_tile_r[MAXT];
__device__ int   g_ntiles;
__device__ __align__(16) float g_h[(size_t)NPAIR * HPAD];
__device__ __align__(16) float g_acc[(size_t)N_TOK * E_DIM];

// ---------------- helpers ----------------
__device__ __forceinline__ uint32_t f2tf32(float f) {
    uint32_t u;
    asm("cvt.rna.tf32.f32 %0, %1;" : "=r"(u) : "f"(f));
    return u;
}
__device__ __forceinline__ void mma8(float d[4], const uint32_t a[4], const uint32_t b[2]) {
    asm volatile(
        "mma.sync.aligned.m16n8k8.row.col.f32.tf32.tf32.f32 "
        "{%0,%1,%2,%3}, {%4,%5,%6,%7}, {%8,%9}, {%0,%1,%2,%3};"
        : "+f"(d[0]), "+f"(d[1]), "+f"(d[2]), "+f"(d[3])
        : "r"(a[0]), "r"(a[1]), "r"(a[2]), "r"(a[3]), "r"(b[0]), "r"(b[1]));
}

// ---------------- small kernels ----------------
__global__ void k_init(const float* __restrict__ x) {
    int i = blockIdx.x * blockDim.x + threadIdx.x;
    if (i < NEXP) g_cnt[i] = 0;
    ((float4*)g_acc)[i] = ((const float4*)x)[i];
}

__global__ void k_router(const float* __restrict__ x, const float* __restrict__ Wr) {
    int warp = (blockIdx.x * blockDim.x + threadIdx.x) >> 5;
    int lane = threadIdx.x & 31;
    if (warp >= N_TOK) return;
    const float* xr = x + (size_t)warp * E_DIM;
    float acc[NEXP];
#pragma unroll
    for (int c = 0; c < NEXP; c++) acc[c] = 0.f;
    for (int k = lane; k < E_DIM; k += 32) {
        float xv = xr[k];
#pragma unroll
        for (int c = 0; c < NEXP; c++) acc[c] += xv * Wr[c * E_DIM + k];
    }
#pragma unroll
    for (int c = 0; c < NEXP; c++)
#pragma unroll
        for (int o = 16; o > 0; o >>= 1) acc[c] += __shfl_xor_sync(0xffffffffu, acc[c], o);
    if (lane == 0) {
        int b0 = 0; float v0 = acc[0];
#pragma unroll
        for (int c = 1; c < NEXP; c++) if (acc[c] > v0) { v0 = acc[c]; b0 = c; }
        int b1 = -1; float v1 = -3.4e38f;
#pragma unroll
        for (int c = 0; c < NEXP; c++) if (c != b0 && acc[c] > v1) { v1 = acc[c]; b1 = c; }
        float t = expf(v1 - v0);
        float w0 = 1.f / (1.f + t);
        g_te[warp * 2 + 0] = b0; g_tw[warp * 2 + 0] = w0;
        g_te[warp * 2 + 1] = b1; g_tw[warp * 2 + 1] = t * w0;
        atomicAdd(&g_cnt[b0], 1);
        atomicAdd(&g_cnt[b1], 1);
    }
}

__global__ void k_prefix() {
    if (threadIdx.x == 0 && blockIdx.x == 0) {
        int s = 0;
        for (int c = 0; c < NEXP; c++) { g_off[c] = s; g_cur[c] = s; s += g_cnt[c]; }
        g_off[NEXP] = s;
        int t = 0;
        for (int c = 0; c < NEXP; c++)
            for (int r = g_off[c]; r < g_off[c + 1]; r += 64) {
                g_tile_e[t] = c; g_tile_r[t] = r; t++;
            }
        g_ntiles = t;
    }
}

__global__ void k_scatter() {
    int n = blockIdx.x * blockDim.x + threadIdx.x;
    if (n >= N_TOK) return;
#pragma unroll
    for (int k = 0; k < 2; k++) {
        int e = g_te[n * 2 + k];
        int slot = atomicAdd(&g_cur[e], 1);
        g_tok[slot] = n;
        g_wt[slot]  = g_tw[n * 2 + k];
    }
}

// ============ GEMM1: h = silu(X@Wv+bv)*(X@Wg+bg), tf32 mma.sync ============
// CTA: 64 tokens x 64 cols, computes BOTH V (warps 0-3) and G (warps 4-7).
// smem fragment-packed: A[miG(4)][ks(4)][lane(32)][4regs], B[nt(8)][ks(4)][lane][2regs]
__global__ void __launch_bounds__(256, 2) k_gemm1(
    const float* __restrict__ x,
    const float* __restrict__ Wv, const float* __restrict__ bv,
    const float* __restrict__ Wg, const float* __restrict__ bg)
{
    int tile = blockIdx.x;
    if (tile >= g_ntiles) return;
    int e = g_tile_e[tile];
    int rbase = g_tile_r[tile];
    int rend  = g_off[e + 1];
    int cbase = blockIdx.y * 64;

    __shared__ __align__(16) uint32_t sA[2048];   // 4*4*32*4
    __shared__ __align__(16) uint32_t sBv[2048];  // 8*4*32*2
    __shared__ __align__(16) uint32_t sBg[2048];
    __shared__ __align__(16) float    sV[64 * 66];
    __shared__ int      stok[64];

    int t = threadIdx.x, w = t >> 5, l = t & 31;
    if (t < 64) {
        int s = rbase + t;
        stok[t] = g_tok[s < rend ? s : rend - 1];
    }
    __syncthreads();

    const float* WvB = Wv + (size_t)e * E_DIM * H_DIM;
    const float* WgB = Wg + (size_t)e * E_DIM * H_DIM;

    float4 ra[2];
    float  rbv[2][4], rbg[2][4];

    auto ldg = [&](int kb) {
#pragma unroll
        for (int i = 0; i < 2; i++) {
            int flat = t + i * 256;
            {   // A: 64 rows x 8 float4 (x rows stride 1024 -> 16B aligned)
                int row = flat >> 3, c4 = flat & 7;
                ra[i] = *(const float4*)(x + (size_t)stok[row] * E_DIM + kb + c4 * 4);
            }
            {   // B: 32 k x 16 groups of 4. Row stride H_DIM=2730 floats = 10920B
                // (8B-aligned, NOT 16B) -> use float2 loads only.
                int k = flat >> 4, n4 = flat & 15;
                int gc = cbase + n4 * 4;
                const float* pv = WvB + (size_t)(kb + k) * H_DIM + gc;
                const float* pg = WgB + (size_t)(kb + k) * H_DIM + gc;
                if (gc + 3 < H_DIM) {
                    float2 v0 = *(const float2*)pv;
                    float2 v1 = *(const float2*)(pv + 2);
                    float2 g0 = *(const float2*)pg;
                    float2 g1 = *(const float2*)(pg + 2);
                    rbv[i][0] = v0.x; rbv[i][1] = v0.y; rbv[i][2] = v1.x; rbv[i][3] = v1.y;
                    rbg[i][0] = g0.x; rbg[i][1] = g0.y; rbg[i][2] = g1.x; rbg[i][3] = g1.y;
                } else {
#pragma unroll
                    for (int q = 0; q < 4; q++) {
                        bool ok = (gc + q) < H_DIM;
                        rbv[i][q] = ok ? pv[q] : 0.f;
                        rbg[i][q] = ok ? pg[q] : 0.f;
                    }
                }
            }
        }
    };

    auto sts = [&]() {
#pragma unroll
        for (int i = 0; i < 2; i++) {
            int flat = t + i * 256;
            {
                int row = flat >> 3, c4 = flat & 7;
                int mi = row >> 4, rr = row & 15;
                const float* f = &ra[i].x;
#pragma unroll
                for (int q = 0; q < 4; q++) {
                    int kk = c4 * 4 + q, ks = kk >> 3, kc = kk & 7;
                    int lane = (rr & 7) * 4 + (kc & 3);
                    int slot = (rr >> 3) + 2 * (kc >> 2);
                    sA[((mi * 4 + ks) * 32 + lane) * 4 + slot] = f2tf32(f[q]);
                }
            }
            {
                int k = flat >> 4, n4 = flat & 15;
                int ks = k >> 3, kr = k & 7;
#pragma unroll
                for (int q = 0; q < 4; q++) {
                    int n = n4 * 4 + q, nt = n >> 3, nr = n & 7;
                    int idx = ((nt * 4 + ks) * 32 + nr * 4 + (kr & 3)) * 2 + (kr >> 2);
                    sBv[idx] = f2tf32(rbv[i][q]);
                    sBg[idx] = f2tf32(rbg[i][q]);
                }
            }
        }
    };

    float acc[2][4][4];
#pragma unroll
    for (int mi = 0; mi < 2; mi++)
#pragma unroll
        for (int nt = 0; nt < 4; nt++)
#pragma unroll
            for (int q = 0; q < 4; q++) acc[mi][nt][q] = 0.f;

    int wm = w & 1, wn = (w >> 1) & 1;
    bool isG = (w >= 4);
    const uint32_t* sB = isG ? sBg : sBv;

    ldg(0);
    for (int c = 0; c < 32; c++) {
        sts();
        __syncthreads();
        if (c < 31) ldg((c + 1) * 32);
#pragma unroll
        for (int ks = 0; ks < 4; ks++) {
            uint32_t af[2][4], bf[4][2];
#pragma unroll
            for (int mi = 0; mi < 2; mi++) {
                uint4 v = *(const uint4*)&sA[(((wm * 2 + mi) * 4 + ks) * 32 + l) * 4];
                af[mi][0] = v.x; af[mi][1] = v.y; af[mi][2] = v.z; af[mi][3] = v.w;
            }
#pragma unroll
            for (int nt = 0; nt < 4; nt++) {
                uint2 v = *(const uint2*)&sB[(((wn * 4 + nt) * 4 + ks) * 32 + l) * 2];
                bf[nt][0] = v.x; bf[nt][1] = v.y;
            }
#pragma unroll
            for (int mi = 0; mi < 2; mi++)
#pragma unroll
                for (int nt = 0; nt < 4; nt++) mma8(acc[mi][nt], af[mi], bf[nt]);
        }
        __syncthreads();
    }

    // epilogue: V warps stage to sV; G warps fuse SwiGLU and write g_h
    if (!isG) {
#pragma unroll
        for (int mi = 0; mi < 2; mi++)
#pragma unroll
            for (int nt = 0; nt < 4; nt++) {
                int r0 = wm * 32 + mi * 16 + (l >> 2);
                int c0 = wn * 32 + nt * 8 + (l & 3) * 2;
                *(float2*)&sV[r0 * 66 + c0]       = make_float2(acc[mi][nt][0], acc[mi][nt][1]);
                *(float2*)&sV[(r0 + 8) * 66 + c0] = make_float2(acc[mi][nt][2], acc[mi][nt][3]);
            }
    }
    __syncthreads();
    if (isG) {
        const float* bvB = bv + (size_t)e * H_DIM;
        const float* bgB = bg + (size_t)e * H_DIM;
#pragma unroll
        for (int mi = 0; mi < 2; mi++)
#pragma unroll
            for (int nt = 0; nt < 4; nt++) {
                int r0 = wm * 32 + mi * 16 + (l >> 2);
                int c0 = wn * 32 + nt * 8 + (l & 3) * 2;
#pragma unroll
                for (int h8 = 0; h8 < 2; h8++) {
                    int row = r0 + h8 * 8;
                    int slot = rbase + row;
                    if (slot < rend) {
                        float2 vv = *(float2*)&sV[row * 66 + c0];
                        int gc = cbase + c0;
                        float o0 = 0.f, o1 = 0.f;
                        if (gc < H_DIM) {
                            float a = vv.x + bvB[gc];
                            float g = acc[mi][nt][h8 * 2] + bgB[gc];
                            o0 = a / (1.f + __expf(-a)) * g;
                        }
                        if (gc + 1 < H_DIM) {
                            float a = vv.y + bvB[gc + 1];
                            float g = acc[mi][nt][h8 * 2 + 1] + bgB[gc + 1];
                            o1 = a / (1.f + __expf(-a)) * g;
                        }
                        *(float2*)&g_h[(size_t)slot * HPAD + gc] = make_float2(o0, o1);
                    }
                }
            }
    }
}

// ============ GEMM2: acc += w * (h @ Wo + bo), tf32 mma.sync ============
// CTA: 64 tokens x 128 cols; warps 2(M) x 4(N), warp tile 32x32.
__global__ void __launch_bounds__(256, 2) k_gemm2(
    const float* __restrict__ Wo, const float* __restrict__ bo)
{
    int tile = blockIdx.x;
    if (tile >= g_ntiles) return;
    int e = g_tile_e[tile];
    int rbase = g_tile_r[tile];
    int rend  = g_off[e + 1];
    int cbase = blockIdx.y * 128;

    __shared__ __align__(16) uint32_t sA[2048];   // 4*4*32*4
    __shared__ __align__(16) uint32_t sB[4096];   // 16*4*32*2

    int t = threadIdx.x, w = t >> 5, l = t & 31;
    const float* WoB = Wo + (size_t)e * H_DIM * E_DIM;

    float4 ra[2], rb[4];

    auto ldg = [&](int kb) {
#pragma unroll
        for (int i = 0; i < 2; i++) {
            int flat = t + i * 256;
            int row = flat >> 3, c4 = flat & 7;
            int slot = rbase + row; if (slot >= rend) slot = rend - 1;
            ra[i] = *(const float4*)(g_h + (size_t)slot * HPAD + kb + c4 * 4);
        }
#pragma unroll
        for (int i = 0; i < 4; i++) {
            int flat = t + i * 256;
            int k = flat >> 5, n4 = flat & 31;
            int gk = kb + k;
            if (gk < H_DIM)
                rb[i] = *(const float4*)(WoB + (size_t)gk * E_DIM + cbase + n4 * 4);
            else
                rb[i] = make_float4(0.f, 0.f, 0.f, 0.f);
        }
    };

    auto sts = [&]() {
#pragma unroll
        for (int i = 0; i < 2; i++) {
            int flat = t + i * 256;
            int row = flat >> 3, c4 = flat & 7;
            int mi = row >> 4, rr = row & 15;
            const float* f = &ra[i].x;
#pragma unroll
            for (int q = 0; q < 4; q++) {
                int kk = c4 * 4 + q, ks = kk >> 3, kc = kk & 7;
                int lane = (rr & 7) * 4 + (kc & 3);
                int slot = (rr >> 3) + 2 * (kc >> 2);
                sA[((mi * 4 + ks) * 32 + lane) * 4 + slot] = f2tf32(f[q]);
            }
        }
#pragma unroll
        for (int i = 0; i < 4; i++) {
            int flat = t + i * 256;
            int k = flat >> 5, n4 = flat & 31;
            int ks = k >> 3, kr = k & 7;
            const float* f = &rb[i].x;
#pragma unroll
            for (int q = 0; q < 4; q++) {
                int n = n4 * 4 + q, nt = n >> 3, nr = n & 7;
                sB[((nt * 4 + ks) * 32 + nr * 4 + (kr & 3)) * 2 + (kr >> 2)] = f2tf32(f[q]);
            }
        }
    };

    float acc[2][4][4];
#pragma unroll
    for (int mi = 0; mi < 2; mi++)
#pragma unroll
        for (int nt = 0; nt < 4; nt++)
#pragma unroll
            for (int q = 0; q < 4; q++) acc[mi][nt][q] = 0.f;

    int wm = w & 1, wn = w >> 1;   // wn 0..3

    ldg(0);
    const int NC = KPAD / 32;  // 86
    for (int c = 0; c < NC; c++) {
        sts();
        __syncthreads();
        if (c < NC - 1) ldg((c + 1) * 32);
#pragma unroll
        for (int ks = 0; ks < 4; ks++) {
            uint32_t af[2][4], bf[4][2];
#pragma unroll
            for (int mi = 0; mi < 2; mi++) {
                uint4 v = *(const uint4*)&sA[(((wm * 2 + mi) * 4 + ks) * 32 + l) * 4];
                af[mi][0] = v.x; af[mi][1] = v.y; af[mi][2] = v.z; af[mi][3] = v.w;
            }
#pragma unroll
            for (int nt = 0; nt < 4; nt++) {
                uint2 v = *(const uint2*)&sB[(((wn * 4 + nt) * 4 + ks) * 32 + l) * 2];
                bf[nt][0] = v.x; bf[nt][1] = v.y;
            }
#pragma unroll
            for (int mi = 0; mi < 2; mi++)
#pragma unroll
                for (int nt = 0; nt < 4; nt++) mma8(acc[mi][nt], af[mi], bf[nt]);
        }
        __syncthreads();
    }

    const float* boB = bo + (size_t)e * E_DIM;
#pragma unroll
    for (int mi = 0; mi < 2; mi++)
#pragma unroll
        for (int nt = 0; nt < 4; nt++) {
            int r0 = wm * 32 + mi * 16 + (l >> 2);
            int c0 = cbase + wn * 32 + nt * 8 + (l & 3) * 2;
#pragma unroll
            for (int h8 = 0; h8 < 2; h8++) {
                int slot = rbase + r0 + h8 * 8;
                if (slot < rend) {
                    int tok = g_tok[slot];
                    float ww = g_wt[slot];
                    float* dst = g_acc + (size_t)tok * E_DIM;
                    atomicAdd(&dst[c0],     ww * (acc[mi][nt][h8 * 2]     + boB[c0]));
                    atomicAdd(&dst[c0 + 1], ww * (acc[mi][nt][h8 * 2 + 1] + boB[c0 + 1]));
                }
            }
        }
}

// ---------------- LayerNorm ----------------
__global__ void k_ln(const float* __restrict__ lng, const float* __restrict__ lnb,
                     float* __restrict__ out)
{
    int n = blockIdx.x, tid = threadIdx.x;
    const float4* row = (const float4*)(g_acc + (size_t)n * E_DIM);
    float4 v = row[tid];
    float s  = v.x + v.y + v.z + v.w;
    float ss = v.x * v.x + v.y * v.y + v.z * v.z + v.w * v.w;
#pragma unroll
    for (int o = 16; o > 0; o >>= 1) {
        s  += __shfl_xor_sync(0xffffffffu, s,  o);
        ss += __shfl_xor_sync(0xffffffffu, ss, o);
    }
    __shared__ float sred[16];
    int w = tid >> 5, l = tid & 31;
    if (l == 0) { sred[w] = s; sred[8 + w] = ss; }
    __syncthreads();
    if (tid < 32) {
        float a = (tid < 8) ? sred[tid] : 0.f;
        float c = (tid < 8) ? sred[8 + tid] : 0.f;
#pragma unroll
        for (int o = 4; o > 0; o >>= 1) {
            a += __shfl_xor_sync(0xffffffffu, a, o);
            c += __shfl_xor_sync(0xffffffffu, c, o);
        }
        if (tid == 0) { sred[0] = a; sred[1] = c; }
    }
    __syncthreads();
    float mu  = sred[0] * (1.f / E_DIM);
    float var = sred[1] * (1.f / E_DIM) - mu * mu;
    float inv = rsqrtf(var + 1e-5f);
    float4 g4 = ((const float4*)lng)[tid];
    float4 b4 = ((const float4*)lnb)[tid];
    float4 o4;
    o4.x = (v.x - mu) * inv * g4.x + b4.x;
    o4.y = (v.y - mu) * inv * g4.y + b4.y;
    o4.z = (v.z - mu) * inv * g4.z + b4.z;
    o4.w = (v.w - mu) * inv * g4.w + b4.w;
    ((float4*)out)[(size_t)n * (E_DIM / 4) + tid] = o4;
}

// ---------------- launcher ----------------
extern "C" void kernel_launch(void* const* d_in, const int* in_sizes, int n_in,
                              void* d_out, int out_size)
{
    const float* x   = (const float*)d_in[0];
    const float* Wr  = (const float*)d_in[1];
    const float* Wv  = (const float*)d_in[2];
    const float* bv  = (const float*)d_in[3];
    const float* Wg  = (const float*)d_in[4];
    const float* bg  = (const float*)d_in[5];
    const float* Wo  = (const float*)d_in[6];
    const float* bo  = (const float*)d_in[7];
    const float* lng = (const float*)d_in[8];
    const float* lnb = (const float*)d_in[9];
    float* out = (float*)d_out;

    k_init<<<(N_TOK * E_DIM / 4) / 256, 256>>>(x);
    k_router<<<(N_TOK * 32) / 256, 256>>>(x, Wr);
    k_prefix<<<1, 32>>>();
    k_scatter<<<N_TOK / 256, 256>>>();

    dim3 g1(MAXT, KPAD / 64);   // (136, 43) ; x = token tile for weight L2 reuse
    k_gemm1<<<g1, 256>>>(x, Wv, bv, Wg, bg);

    dim3 g2(MAXT, E_DIM / 128); // (136, 8)
    k_gemm2<<<g2, 256>>>(Wo, bo);

    k_ln<<<N_TOK, 256>>>(lng, lnb, out);
}

// round 5
// speedup vs baseline: 6.8872x; 5.6271x over previous
#include <cuda_runtime.h>
#include <cuda_fp16.h>
#include <math.h>
#include <stdint.h>

#define N_TOK 4096
#define E_DIM 1024
#define H_DIM 2730
#define HPH   2736          // fp16 weight row pad (×2B = 5472, 16B-aligned)
#define HP2   2752          // g_h fp16 row pad / GEMM2 K extent (43*64)
#define KP2   2752
#define NEXP  8
#define NPAIR 8192
#define MAXT  136
#define KC    64

// ---------------- device scratch ----------------
__device__ int   g_cnt[NEXP];
__device__ int   g_off[NEXP + 1];
__device__ int   g_cur[NEXP];
__device__ int   g_te[N_TOK * 2];
__device__ float g_tw[N_TOK * 2];
__device__ int   g_tok[NPAIR];
__device__ float g_wt[NPAIR];
__device__ int   g_tile_e[MAXT];
__device__ int   g_tile_r[MAXT];
__device__ int   g_ntiles;
__device__ __align__(16) __half d_wvh[(size_t)NEXP * E_DIM * HPH + 64];
__device__ __align__(16) __half d_wgh[(size_t)NEXP * E_DIM * HPH + 64];
__device__ __align__(16) __half d_woh[(size_t)NEXP * KP2 * E_DIM];
__device__ __align__(16) __half d_xh[(size_t)N_TOK * E_DIM];
__device__ __align__(16) __half d_gh[(size_t)NPAIR * HP2];
__device__ __align__(16) float  g_acc[(size_t)N_TOK * E_DIM];

// ---------------- PTX helpers ----------------
__device__ __forceinline__ uint32_t smem_u32(const void* p) {
    uint32_t a;
    asm("{ .reg .u64 t; cvta.to.shared.u64 t, %1; cvt.u32.u64 %0, t; }" : "=r"(a) : "l"(p));
    return a;
}
__device__ __forceinline__ void cpa16(uint32_t dst, const void* src) {
    asm volatile("cp.async.cg.shared.global [%0], [%1], 16;" :: "r"(dst), "l"(src) : "memory");
}
#define CPA_COMMIT() asm volatile("cp.async.commit_group;" ::: "memory")
#define CPA_WAIT0()  asm volatile("cp.async.wait_group 0;" ::: "memory")
#define LDM4(r, a)                                                              \
    asm volatile("ldmatrix.sync.aligned.m8n8.x4.shared.b16 {%0,%1,%2,%3}, [%4];" \
        : "=r"((r)[0]), "=r"((r)[1]), "=r"((r)[2]), "=r"((r)[3]) : "r"(a))
#define LDM4T(r, a)                                                             \
    asm volatile("ldmatrix.sync.aligned.m8n8.x4.trans.shared.b16 {%0,%1,%2,%3}, [%4];" \
        : "=r"((r)[0]), "=r"((r)[1]), "=r"((r)[2]), "=r"((r)[3]) : "r"(a))

__device__ __forceinline__ void mma16(float d[4], const uint32_t a[4], uint32_t b0, uint32_t b1) {
    asm volatile(
        "mma.sync.aligned.m16n8k16.row.col.f32.f16.f16.f32 "
        "{%0,%1,%2,%3}, {%4,%5,%6,%7}, {%8,%9}, {%0,%1,%2,%3};"
        : "+f"(d[0]), "+f"(d[1]), "+f"(d[2]), "+f"(d[3])
        : "r"(a[0]), "r"(a[1]), "r"(a[2]), "r"(a[3]), "r"(b0), "r"(b1));
}

// ---------------- weight conversion ----------------
__global__ void k_cvt_vg(const float* __restrict__ Wv, const float* __restrict__ Wg) {
    size_t p = (size_t)blockIdx.x * blockDim.x + threadIdx.x;
    if (p >= (size_t)NEXP * E_DIM * (HPH / 2)) return;
    int n2 = (int)(p % (HPH / 2));
    size_t r = p / (HPH / 2);          // e*E_DIM + k
    int n = n2 * 2;
    size_t src = r * H_DIM + n;
    float v0 = (n     < H_DIM) ? Wv[src]     : 0.f;
    float v1 = (n + 1 < H_DIM) ? Wv[src + 1] : 0.f;
    float q0 = (n     < H_DIM) ? Wg[src]     : 0.f;
    float q1 = (n + 1 < H_DIM) ? Wg[src + 1] : 0.f;
    ((__half2*)d_wvh)[r * (HPH / 2) + n2] = __floats2half2_rn(v0, v1);
    ((__half2*)d_wgh)[r * (HPH / 2) + n2] = __floats2half2_rn(q0, q1);
}

__global__ void k_cvt_o(const float* __restrict__ Wo) {
    size_t p = (size_t)blockIdx.x * blockDim.x + threadIdx.x;
    if (p >= (size_t)NEXP * KP2 * (E_DIM / 2)) return;
    int n2 = (int)(p & (E_DIM / 2 - 1));
    size_t r = p >> 9;                 // e*KP2 + k
    int k = (int)(r % KP2);
    int e = (int)(r / KP2);
    int n = n2 * 2;
    float v0 = 0.f, v1 = 0.f;
    if (k < H_DIM) {
        size_t src = ((size_t)e * H_DIM + k) * E_DIM + n;
        v0 = Wo[src]; v1 = Wo[src + 1];
    }
    ((__half2*)d_woh)[r * (E_DIM / 2) + n2] = __floats2half2_rn(v0, v1);
}

// ---------------- init: residual copy + x->fp16 + zero counters -------------
__global__ void k_init(const float* __restrict__ x) {
    int i = blockIdx.x * blockDim.x + threadIdx.x;
    if (i < NEXP) g_cnt[i] = 0;
    float4 v = ((const float4*)x)[i];
    ((float4*)g_acc)[i] = v;
    ((__half2*)d_xh)[2 * i]     = __floats2half2_rn(v.x, v.y);
    ((__half2*)d_xh)[2 * i + 1] = __floats2half2_rn(v.z, v.w);
}

// ---------------- router ----------------
__global__ void k_router(const float* __restrict__ x, const float* __restrict__ Wr) {
    int warp = (blockIdx.x * blockDim.x + threadIdx.x) >> 5;
    int lane = threadIdx.x & 31;
    if (warp >= N_TOK) return;
    const float* xr = x + (size_t)warp * E_DIM;
    float acc[NEXP];
#pragma unroll
    for (int c = 0; c < NEXP; c++) acc[c] = 0.f;
    for (int k = lane; k < E_DIM; k += 32) {
        float xv = xr[k];
#pragma unroll
        for (int c = 0; c < NEXP; c++) acc[c] += xv * Wr[c * E_DIM + k];
    }
#pragma unroll
    for (int c = 0; c < NEXP; c++)
#pragma unroll
        for (int o = 16; o > 0; o >>= 1) acc[c] += __shfl_xor_sync(0xffffffffu, acc[c], o);
    if (lane == 0) {
        int b0 = 0; float v0 = acc[0];
#pragma unroll
        for (int c = 1; c < NEXP; c++) if (acc[c] > v0) { v0 = acc[c]; b0 = c; }
        int b1 = -1; float v1 = -3.4e38f;
#pragma unroll
        for (int c = 0; c < NEXP; c++) if (c != b0 && acc[c] > v1) { v1 = acc[c]; b1 = c; }
        float t = expf(v1 - v0);
        float w0 = 1.f / (1.f + t);
        g_te[warp * 2 + 0] = b0; g_tw[warp * 2 + 0] = w0;
        g_te[warp * 2 + 1] = b1; g_tw[warp * 2 + 1] = t * w0;
        atomicAdd(&g_cnt[b0], 1);
        atomicAdd(&g_cnt[b1], 1);
    }
}

// ---------------- prefix + scatter (single block) ----------------
__global__ void k_scatter_one() {
    int t = threadIdx.x;
    if (t == 0) {
        int s = 0;
        for (int c = 0; c < NEXP; c++) { g_off[c] = s; g_cur[c] = s; s += g_cnt[c]; }
        g_off[NEXP] = s;
        int tt = 0;
        for (int c = 0; c < NEXP; c++)
            for (int r = g_off[c]; r < g_off[c + 1]; r += 64) {
                g_tile_e[tt] = c; g_tile_r[tt] = r; tt++;
            }
        g_ntiles = tt;
    }
    __syncthreads();
    for (int n = t; n < N_TOK; n += blockDim.x) {
#pragma unroll
        for (int k = 0; k < 2; k++) {
            int e = g_te[n * 2 + k];
            int slot = atomicAdd(&g_cur[e], 1);
            g_tok[slot] = n;
            g_wt[slot]  = g_tw[n * 2 + k];
        }
    }
}

// ============ GEMM1: fp16 mma, h = silu(X@Wv+bv)*(X@Wg+bg) ============
// CTA 64 tok x 64 H-cols; warps 0-3 -> V, 4-7 -> G (shared A). warp tile 32x32.
// stage: A 64x(64+8 pad)halfs @144B/row = 9216B; Bv,Bg same. 2 stages.
#define ST1   27648
#define SM1   (256 + 2 * ST1)
#define ST2   (9216 + 17408)
#define SM2   (2 * ST2)

__global__ void __launch_bounds__(256, 2) k_gemm1(
    const float* __restrict__ bv, const float* __restrict__ bg)
{
    int tile = blockIdx.x;
    if (tile >= g_ntiles) return;
    int e = g_tile_e[tile];
    int rbase = g_tile_r[tile];
    int rend  = g_off[e + 1];
    int cbase = blockIdx.y * 64;

    extern __shared__ __align__(16) char dsm[];
    int* stok = (int*)dsm;
    uint32_t st0 = smem_u32(dsm + 256);
    int t = threadIdx.x, w = t >> 5, l = t & 31;

    if (t < 64) {
        int s = rbase + t;
        stok[t] = g_tok[s < rend ? s : rend - 1];
    }
    __syncthreads();

    const __half* wvp = d_wvh + ((size_t)e * E_DIM) * HPH + cbase;
    const __half* wgp = d_wgh + ((size_t)e * E_DIM) * HPH + cbase;

    auto fill = [&](int c) {
        uint32_t sb = st0 + (c & 1) * ST1;
        int kb = c * KC;
#pragma unroll
        for (int i = 0; i < 2; i++) {
            int ch = t + i * 256;
            int row = ch >> 3, cc = ch & 7;
            uint32_t off = row * 144 + cc * 16;
            cpa16(sb + off,         d_xh + (size_t)stok[row] * E_DIM + kb + cc * 8);
            cpa16(sb + 9216 + off,  wvp + (size_t)(kb + row) * HPH + cc * 8);
            cpa16(sb + 18432 + off, wgp + (size_t)(kb + row) * HPH + cc * 8);
        }
    };

    float acc[2][4][4];
#pragma unroll
    for (int mi = 0; mi < 2; mi++)
#pragma unroll
        for (int nt = 0; nt < 4; nt++)
#pragma unroll
            for (int q = 0; q < 4; q++) acc[mi][nt][q] = 0.f;

    int wm = w & 1, wn = (w >> 1) & 1;
    bool isG = (w >= 4);
    int g = l >> 3, lr = l & 7;
    uint32_t a_off = ((g & 1) * 8 + lr) * 144 + (g >> 1) * 16;

    fill(0); CPA_COMMIT();
    for (int c = 0; c < 16; c++) {
        CPA_WAIT0();
        __syncthreads();
        if (c + 1 < 16) { fill(c + 1); CPA_COMMIT(); }
        uint32_t sb = st0 + (c & 1) * ST1;
        uint32_t aB = sb + wm * 32 * 144;
        uint32_t bB = sb + (isG ? 18432u : 9216u) + wn * 64;
#pragma unroll
        for (int ks = 0; ks < 4; ks++) {
            uint32_t af[2][4], bf[2][4];
            LDM4(af[0], aB + ks * 32 + a_off);
            LDM4(af[1], aB + 16 * 144 + ks * 32 + a_off);
            LDM4T(bf[0], bB + ks * 16 * 144 + a_off);
            LDM4T(bf[1], bB + ks * 16 * 144 + 32 + a_off);
#pragma unroll
            for (int mi = 0; mi < 2; mi++) {
                mma16(acc[mi][0], af[mi], bf[0][0], bf[0][1]);
                mma16(acc[mi][1], af[mi], bf[0][2], bf[0][3]);
                mma16(acc[mi][2], af[mi], bf[1][0], bf[1][1]);
                mma16(acc[mi][3], af[mi], bf[1][2], bf[1][3]);
            }
        }
    }

    // epilogue: V warps stage to sV (overlay stage0); G warps fuse SwiGLU
    __syncthreads();
    float* sV = (float*)(dsm + 256);
    if (!isG) {
#pragma unroll
        for (int mi = 0; mi < 2; mi++)
#pragma unroll
            for (int nt = 0; nt < 4; nt++) {
                int r0 = wm * 32 + mi * 16 + (l >> 2);
                int c0 = wn * 32 + nt * 8 + (l & 3) * 2;
                *(float2*)&sV[r0 * 66 + c0]       = make_float2(acc[mi][nt][0], acc[mi][nt][1]);
                *(float2*)&sV[(r0 + 8) * 66 + c0] = make_float2(acc[mi][nt][2], acc[mi][nt][3]);
            }
    }
    __syncthreads();
    if (isG) {
        const float* bvB = bv + (size_t)e * H_DIM;
        const float* bgB = bg + (size_t)e * H_DIM;
#pragma unroll
        for (int mi = 0; mi < 2; mi++)
#pragma unroll
            for (int nt = 0; nt < 4; nt++) {
                int r0 = wm * 32 + mi * 16 + (l >> 2);
                int c0 = wn * 32 + nt * 8 + (l & 3) * 2;
#pragma unroll
                for (int h8 = 0; h8 < 2; h8++) {
                    int row = r0 + h8 * 8;
                    int slot = rbase + row;
                    if (slot < rend) {
                        float2 vv = *(float2*)&sV[row * 66 + c0];
                        int gc = cbase + c0;
                        float o0 = 0.f, o1 = 0.f;
                        if (gc < H_DIM) {
                            float a = vv.x + bvB[gc];
                            float gg = acc[mi][nt][h8 * 2] + bgB[gc];
                            o0 = a / (1.f + __expf(-a)) * gg;
                        }
                        if (gc + 1 < H_DIM) {
                            float a = vv.y + bvB[gc + 1];
                            float gg = acc[mi][nt][h8 * 2 + 1] + bgB[gc + 1];
                            o1 = a / (1.f + __expf(-a)) * gg;
                        }
                        *(__half2*)&d_gh[(size_t)slot * HP2 + gc] = __floats2half2_rn(o0, o1);
                    }
                }
            }
    }
}

// ============ GEMM2: acc += w * (h @ Wo + bo), fp16 mma ============
// CTA 64 tok x 128 E-cols; warps 2(M) x 4(N), warp tile 32x32.
// stage: A 64x144B = 9216, B 64 k-rows x (128+8)halfs @272B = 17408.
__global__ void __launch_bounds__(256, 2) k_gemm2(const float* __restrict__ bo)
{
    int tile = blockIdx.x;
    if (tile >= g_ntiles) return;
    int e = g_tile_e[tile];
    int rbase = g_tile_r[tile];
    int rend  = g_off[e + 1];
    int cbase = blockIdx.y * 128;

    extern __shared__ __align__(16) char dsm[];
    uint32_t st0 = smem_u32(dsm);
    int t = threadIdx.x, w = t >> 5, l = t & 31;

    const __half* wop = d_woh + (size_t)e * KP2 * E_DIM + cbase;

    auto fill = [&](int c) {
        uint32_t sb = st0 + (c & 1) * ST2;
        int kb = c * KC;
#pragma unroll
        for (int i = 0; i < 2; i++) {
            int ch = t + i * 256;
            int row = ch >> 3, cc = ch & 7;
            int slot = rbase + row; if (slot >= rend) slot = rend - 1;
            cpa16(sb + row * 144 + cc * 16, d_gh + (size_t)slot * HP2 + kb + cc * 8);
        }
#pragma unroll
        for (int i = 0; i < 4; i++) {
            int ch = t + i * 256;
            int kr = ch >> 4, cc = ch & 15;
            cpa16(sb + 9216 + kr * 272 + cc * 16, wop + (size_t)(kb + kr) * E_DIM + cc * 8);
        }
    };

    float acc[2][4][4];
#pragma unroll
    for (int mi = 0; mi < 2; mi++)
#pragma unroll
        for (int nt = 0; nt < 4; nt++)
#pragma unroll
            for (int q = 0; q < 4; q++) acc[mi][nt][q] = 0.f;

    int wm = w & 1, wn = w >> 1;
    int g = l >> 3, lr = l & 7;
    uint32_t a_off = ((g & 1) * 8 + lr) * 144 + (g >> 1) * 16;
    uint32_t b_off = ((g & 1) * 8 + lr) * 272 + (g >> 1) * 16;

    fill(0); CPA_COMMIT();
    const int NC = KP2 / KC;  // 43
    for (int c = 0; c < NC; c++) {
        CPA_WAIT0();
        __syncthreads();
        if (c + 1 < NC) { fill(c + 1); CPA_COMMIT(); }
        uint32_t sb = st0 + (c & 1) * ST2;
        uint32_t aB = sb + wm * 32 * 144;
        uint32_t bB = sb + 9216 + wn * 64;
#pragma unroll
        for (int ks = 0; ks < 4; ks++) {
            uint32_t af[2][4], bf[2][4];
            LDM4(af[0], aB + ks * 32 + a_off);
            LDM4(af[1], aB + 16 * 144 + ks * 32 + a_off);
            LDM4T(bf[0], bB + ks * 16 * 272 + b_off);
            LDM4T(bf[1], bB + ks * 16 * 272 + 32 + b_off);
#pragma unroll
            for (int mi = 0; mi < 2; mi++) {
                mma16(acc[mi][0], af[mi], bf[0][0], bf[0][1]);
                mma16(acc[mi][1], af[mi], bf[0][2], bf[0][3]);
                mma16(acc[mi][2], af[mi], bf[1][0], bf[1][1]);
                mma16(acc[mi][3], af[mi], bf[1][2], bf[1][3]);
            }
        }
    }

    const float* boB = bo + (size_t)e * E_DIM;
#pragma unroll
    for (int mi = 0; mi < 2; mi++)
#pragma unroll
        for (int nt = 0; nt < 4; nt++) {
            int r0 = wm * 32 + mi * 16 + (l >> 2);
            int c0 = cbase + wn * 32 + nt * 8 + (l & 3) * 2;
#pragma unroll
            for (int h8 = 0; h8 < 2; h8++) {
                int slot = rbase + r0 + h8 * 8;
                if (slot < rend) {
                    int tok = g_tok[slot];
                    float ww = g_wt[slot];
                    float* dst = g_acc + (size_t)tok * E_DIM;
                    atomicAdd(&dst[c0],     ww * (acc[mi][nt][h8 * 2]     + boB[c0]));
                    atomicAdd(&dst[c0 + 1], ww * (acc[mi][nt][h8 * 2 + 1] + boB[c0 + 1]));
                }
            }
        }
}

// ---------------- LayerNorm ----------------
__global__ void k_ln(const float* __restrict__ lng, const float* __restrict__ lnb,
                     float* __restrict__ out)
{
    int n = blockIdx.x, tid = threadIdx.x;
    const float4* row = (const float4*)(g_acc + (size_t)n * E_DIM);
    float4 v = row[tid];
    float s  = v.x + v.y + v.z + v.w;
    float ss = v.x * v.x + v.y * v.y + v.z * v.z + v.w * v.w;
#pragma unroll
    for (int o = 16; o > 0; o >>= 1) {
        s  += __shfl_xor_sync(0xffffffffu, s,  o);
        ss += __shfl_xor_sync(0xffffffffu, ss, o);
    }
    __shared__ float sred[16];
    int w = tid >> 5, l = tid & 31;
    if (l == 0) { sred[w] = s; sred[8 + w] = ss; }
    __syncthreads();
    if (tid < 32) {
        float a = (tid < 8) ? sred[tid] : 0.f;
        float c = (tid < 8) ? sred[8 + tid] : 0.f;
#pragma unroll
        for (int o = 4; o > 0; o >>= 1) {
            a += __shfl_xor_sync(0xffffffffu, a, o);
            c += __shfl_xor_sync(0xffffffffu, c, o);
        }
        if (tid == 0) { sred[0] = a; sred[1] = c; }
    }
    __syncthreads();
    float mu  = sred[0] * (1.f / E_DIM);
    float var = sred[1] * (1.f / E_DIM) - mu * mu;
    float inv = rsqrtf(var + 1e-5f);
    float4 g4 = ((const float4*)lng)[tid];
    float4 b4 = ((const float4*)lnb)[tid];
    float4 o4;
    o4.x = (v.x - mu) * inv * g4.x + b4.x;
    o4.y = (v.y - mu) * inv * g4.y + b4.y;
    o4.z = (v.z - mu) * inv * g4.z + b4.z;
    o4.w = (v.w - mu) * inv * g4.w + b4.w;
    ((float4*)out)[(size_t)n * (E_DIM / 4) + tid] = o4;
}

// ---------------- launcher ----------------
extern "C" void kernel_launch(void* const* d_in, const int* in_sizes, int n_in,
                              void* d_out, int out_size)
{
    const float* x   = (const float*)d_in[0];
    const float* Wr  = (const float*)d_in[1];
    const float* Wv  = (const float*)d_in[2];
    const float* bv  = (const float*)d_in[3];
    const float* Wg  = (const float*)d_in[4];
    const float* bg  = (const float*)d_in[5];
    const float* Wo  = (const float*)d_in[6];
    const float* bo  = (const float*)d_in[7];
    const float* lng = (const float*)d_in[8];
    const float* lnb = (const float*)d_in[9];
    float* out = (float*)d_out;

    static int configured = 0;
    cudaFuncSetAttribute(k_gemm1, cudaFuncAttributeMaxDynamicSharedMemorySize, SM1);
    cudaFuncSetAttribute(k_gemm2, cudaFuncAttributeMaxDynamicSharedMemorySize, SM2);
    (void)configured;

    {   // launch index 0,1: weight conversion
        size_t pvg = (size_t)NEXP * E_DIM * (HPH / 2);
        k_cvt_vg<<<(unsigned)((pvg + 255) / 256), 256>>>(Wv, Wg);
        size_t po = (size_t)NEXP * KP2 * (E_DIM / 2);
        k_cvt_o<<<(unsigned)((po + 255) / 256), 256>>>(Wo);
    }
    k_init<<<(N_TOK * E_DIM / 4) / 256, 256>>>(x);          // 2
    k_router<<<(N_TOK * 32) / 256, 256>>>(x, Wr);           // 3
    k_scatter_one<<<1, 1024>>>();                           // 4

    dim3 g1(MAXT, 43);   // 5  <- ncu -s 5 captures this
    k_gemm1<<<g1, 256, SM1>>>(bv, bg);

    dim3 g2(MAXT, 8);    // 6
    k_gemm2<<<g2, 256, SM2>>>(bo);

    k_ln<<<N_TOK, 256>>>(lng, lnb, out);                    // 7
}

// round 6
// speedup vs baseline: 8.4883x; 1.2325x over previous
#include <cuda_runtime.h>
#include <cuda_fp16.h>
#include <math.h>
#include <stdint.h>

#define N_TOK 4096
#define E_DIM 1024
#define H_DIM 2730
#define HPH   2736          // fp16 weight row pad (×2B = 5472, 16B-aligned)
#define HP2   2752          // g_h fp16 row pad / GEMM2 K extent (43*64)
#define KP2   2752
#define NEXP  8
#define NPAIR 8192
#define MAXT  71            // 8192/128 + 7
#define KC    64

// ---------------- device scratch ----------------
__device__ int   g_cnt[NEXP];
__device__ int   g_off[NEXP + 1];
__device__ int   g_cur[NEXP];
__device__ int   g_te[N_TOK * 2];
__device__ float g_tw[N_TOK * 2];
__device__ int   g_tok[NPAIR];
__device__ float g_wt[NPAIR];
__device__ int   g_tile_e[MAXT];
__device__ int   g_tile_r[MAXT];
__device__ int   g_ntiles;
__device__ __align__(16) __half d_wvh[(size_t)NEXP * E_DIM * HPH + 64];
__device__ __align__(16) __half d_wgh[(size_t)NEXP * E_DIM * HPH + 64];
__device__ __align__(16) __half d_woh[(size_t)NEXP * KP2 * E_DIM];
__device__ __align__(16) __half d_xh[(size_t)N_TOK * E_DIM];
__device__ __align__(16) __half d_gh[(size_t)NPAIR * HP2];
__device__ __align__(16) float  g_acc[(size_t)N_TOK * E_DIM];

// ---------------- PTX helpers ----------------
__device__ __forceinline__ uint32_t smem_u32(const void* p) {
    uint32_t a;
    asm("{ .reg .u64 t; cvta.to.shared.u64 t, %1; cvt.u32.u64 %0, t; }" : "=r"(a) : "l"(p));
    return a;
}
__device__ __forceinline__ void cpa16(uint32_t dst, const void* src) {
    asm volatile("cp.async.cg.shared.global [%0], [%1], 16;" :: "r"(dst), "l"(src) : "memory");
}
#define CPA_COMMIT() asm volatile("cp.async.commit_group;" ::: "memory")
#define CPA_WAIT0()  asm volatile("cp.async.wait_group 0;" ::: "memory")
#define LDM4(r, a)                                                              \
    asm volatile("ldmatrix.sync.aligned.m8n8.x4.shared.b16 {%0,%1,%2,%3}, [%4];" \
        : "=r"((r)[0]), "=r"((r)[1]), "=r"((r)[2]), "=r"((r)[3]) : "r"(a))
#define LDM4T(r, a)                                                             \
    asm volatile("ldmatrix.sync.aligned.m8n8.x4.trans.shared.b16 {%0,%1,%2,%3}, [%4];" \
        : "=r"((r)[0]), "=r"((r)[1]), "=r"((r)[2]), "=r"((r)[3]) : "r"(a))

__device__ __forceinline__ void mma16(float d[4], const uint32_t a[4], uint32_t b0, uint32_t b1) {
    asm volatile(
        "mma.sync.aligned.m16n8k16.row.col.f32.f16.f16.f32 "
        "{%0,%1,%2,%3}, {%4,%5,%6,%7}, {%8,%9}, {%0,%1,%2,%3};"
        : "+f"(d[0]), "+f"(d[1]), "+f"(d[2]), "+f"(d[3])
        : "r"(a[0]), "r"(a[1]), "r"(a[2]), "r"(a[3]), "r"(b0), "r"(b1));
}

// ---------------- weight conversion ----------------
__global__ void k_cvt_vg(const float* __restrict__ Wv, const float* __restrict__ Wg) {
    size_t p = (size_t)blockIdx.x * blockDim.x + threadIdx.x;
    if (p >= (size_t)NEXP * E_DIM * (HPH / 2)) return;
    int n2 = (int)(p % (HPH / 2));
    size_t r = p / (HPH / 2);
    int n = n2 * 2;
    size_t src = r * H_DIM + n;
    float v0 = (n     < H_DIM) ? Wv[src]     : 0.f;
    float v1 = (n + 1 < H_DIM) ? Wv[src + 1] : 0.f;
    float q0 = (n     < H_DIM) ? Wg[src]     : 0.f;
    float q1 = (n + 1 < H_DIM) ? Wg[src + 1] : 0.f;
    ((__half2*)d_wvh)[r * (HPH / 2) + n2] = __floats2half2_rn(v0, v1);
    ((__half2*)d_wgh)[r * (HPH / 2) + n2] = __floats2half2_rn(q0, q1);
}

__global__ void k_cvt_o(const float* __restrict__ Wo) {
    size_t p = (size_t)blockIdx.x * blockDim.x + threadIdx.x;
    if (p >= (size_t)NEXP * KP2 * (E_DIM / 2)) return;
    int n2 = (int)(p & (E_DIM / 2 - 1));
    size_t r = p >> 9;
    int k = (int)(r % KP2);
    int e = (int)(r / KP2);
    int n = n2 * 2;
    float v0 = 0.f, v1 = 0.f;
    if (k < H_DIM) {
        size_t src = ((size_t)e * H_DIM + k) * E_DIM + n;
        v0 = Wo[src]; v1 = Wo[src + 1];
    }
    ((__half2*)d_woh)[r * (E_DIM / 2) + n2] = __floats2half2_rn(v0, v1);
}

// ---------------- init ----------------
__global__ void k_init(const float* __restrict__ x) {
    int i = blockIdx.x * blockDim.x + threadIdx.x;
    if (i < NEXP) g_cnt[i] = 0;
    float4 v = ((const float4*)x)[i];
    ((float4*)g_acc)[i] = v;
    ((__half2*)d_xh)[2 * i]     = __floats2half2_rn(v.x, v.y);
    ((__half2*)d_xh)[2 * i + 1] = __floats2half2_rn(v.z, v.w);
}

// ---------------- router ----------------
__global__ void k_router(const float* __restrict__ x, const float* __restrict__ Wr) {
    int warp = (blockIdx.x * blockDim.x + threadIdx.x) >> 5;
    int lane = threadIdx.x & 31;
    if (warp >= N_TOK) return;
    const float* xr = x + (size_t)warp * E_DIM;
    float acc[NEXP];
#pragma unroll
    for (int c = 0; c < NEXP; c++) acc[c] = 0.f;
    for (int k = lane; k < E_DIM; k += 32) {
        float xv = xr[k];
#pragma unroll
        for (int c = 0; c < NEXP; c++) acc[c] += xv * Wr[c * E_DIM + k];
    }
#pragma unroll
    for (int c = 0; c < NEXP; c++)
#pragma unroll
        for (int o = 16; o > 0; o >>= 1) acc[c] += __shfl_xor_sync(0xffffffffu, acc[c], o);
    if (lane == 0) {
        int b0 = 0; float v0 = acc[0];
#pragma unroll
        for (int c = 1; c < NEXP; c++) if (acc[c] > v0) { v0 = acc[c]; b0 = c; }
        int b1 = -1; float v1 = -3.4e38f;
#pragma unroll
        for (int c = 0; c < NEXP; c++) if (c != b0 && acc[c] > v1) { v1 = acc[c]; b1 = c; }
        float t = expf(v1 - v0);
        float w0 = 1.f / (1.f + t);
        g_te[warp * 2 + 0] = b0; g_tw[warp * 2 + 0] = w0;
        g_te[warp * 2 + 1] = b1; g_tw[warp * 2 + 1] = t * w0;
        atomicAdd(&g_cnt[b0], 1);
        atomicAdd(&g_cnt[b1], 1);
    }
}

// ---------------- prefix + scatter ----------------
__global__ void k_scatter_one() {
    int t = threadIdx.x;
    if (t == 0) {
        int s = 0;
        for (int c = 0; c < NEXP; c++) { g_off[c] = s; g_cur[c] = s; s += g_cnt[c]; }
        g_off[NEXP] = s;
        int tt = 0;
        for (int c = 0; c < NEXP; c++)
            for (int r = g_off[c]; r < g_off[c + 1]; r += 128) {
                g_tile_e[tt] = c; g_tile_r[tt] = r; tt++;
            }
        g_ntiles = tt;
    }
    __syncthreads();
    for (int n = t; n < N_TOK; n += blockDim.x) {
#pragma unroll
        for (int k = 0; k < 2; k++) {
            int e = g_te[n * 2 + k];
            int slot = atomicAdd(&g_cur[e], 1);
            g_tok[slot] = n;
            g_wt[slot]  = g_tw[n * 2 + k];
        }
    }
}

// ============ GEMM1: fp16 mma, h = silu(X@Wv+bv)*(X@Wg+bg) ============
// CTA 128 tok x 64 H-cols; warps 0-3 -> V, 4-7 -> G (shared A).
// warp tile 64 tok x 32 cols. stage: A 128x144B=18432, Bv 64x144=9216, Bg 9216.
#define ST1   36864
#define SM1   (512 + 2 * ST1)
#define ST2   (18432 + 17408)
#define SM2   (2 * ST2)

__global__ void __launch_bounds__(256, 2) k_gemm1(
    const float* __restrict__ bv, const float* __restrict__ bg)
{
    int tile = blockIdx.x;
    if (tile >= g_ntiles) return;
    int e = g_tile_e[tile];
    int rbase = g_tile_r[tile];
    int rend  = g_off[e + 1];
    int cbase = blockIdx.y * 64;

    extern __shared__ __align__(16) char dsm[];
    int* stok = (int*)dsm;
    uint32_t st0 = smem_u32(dsm + 512);
    int t = threadIdx.x, w = t >> 5, l = t & 31;

    if (t < 128) {
        int s = rbase + t;
        stok[t] = g_tok[s < rend ? s : rend - 1];
    }
    __syncthreads();

    const __half* wvp = d_wvh + ((size_t)e * E_DIM) * HPH + cbase;
    const __half* wgp = d_wgh + ((size_t)e * E_DIM) * HPH + cbase;

    auto fill = [&](int c) {
        uint32_t sb = st0 + (c & 1) * ST1;
        int kb = c * KC;
#pragma unroll
        for (int i = 0; i < 4; i++) {          // A: 128 rows x 8 x 16B
            int ch = t + i * 256;
            int row = ch >> 3, cc = ch & 7;
            cpa16(sb + row * 144 + cc * 16, d_xh + (size_t)stok[row] * E_DIM + kb + cc * 8);
        }
#pragma unroll
        for (int i = 0; i < 2; i++) {          // Bv,Bg: 64 k-rows x 8 x 16B each
            int ch = t + i * 256;
            int kr = ch >> 3, cc = ch & 7;
            uint32_t off = kr * 144 + cc * 16;
            cpa16(sb + 18432 + off, wvp + (size_t)(kb + kr) * HPH + cc * 8);
            cpa16(sb + 27648 + off, wgp + (size_t)(kb + kr) * HPH + cc * 8);
        }
    };

    float acc[4][4][4];
#pragma unroll
    for (int mi = 0; mi < 4; mi++)
#pragma unroll
        for (int nt = 0; nt < 4; nt++)
#pragma unroll
            for (int q = 0; q < 4; q++) acc[mi][nt][q] = 0.f;

    int wl = w & 3;
    int wm = wl & 1, wn = wl >> 1;
    bool isG = (w >= 4);
    int g = l >> 3, lr = l & 7;
    uint32_t frag_off = ((g & 1) * 8 + lr) * 144 + (g >> 1) * 16;

    fill(0); CPA_COMMIT();
    for (int c = 0; c < 16; c++) {
        CPA_WAIT0();
        __syncthreads();
        if (c + 1 < 16) { fill(c + 1); CPA_COMMIT(); }
        uint32_t sb = st0 + (c & 1) * ST1;
        uint32_t aB = sb + wm * 64 * 144;
        uint32_t bB = sb + (isG ? 27648u : 18432u) + wn * 64;
#pragma unroll
        for (int ks = 0; ks < 4; ks++) {
            uint32_t af[4][4], bf[2][4];
#pragma unroll
            for (int mi = 0; mi < 4; mi++)
                LDM4(af[mi], aB + mi * 16 * 144 + ks * 32 + frag_off);
            LDM4T(bf[0], bB + ks * 16 * 144 + frag_off);
            LDM4T(bf[1], bB + ks * 16 * 144 + 32 + frag_off);
#pragma unroll
            for (int mi = 0; mi < 4; mi++) {
                mma16(acc[mi][0], af[mi], bf[0][0], bf[0][1]);
                mma16(acc[mi][1], af[mi], bf[0][2], bf[0][3]);
                mma16(acc[mi][2], af[mi], bf[1][0], bf[1][1]);
                mma16(acc[mi][3], af[mi], bf[1][2], bf[1][3]);
            }
        }
    }

    // epilogue: V warps stage to sV (overlay stage buffers); G warps fuse SwiGLU
    __syncthreads();
    float* sV = (float*)(dsm + 512);
    if (!isG) {
#pragma unroll
        for (int mi = 0; mi < 4; mi++)
#pragma unroll
            for (int nt = 0; nt < 4; nt++) {
                int r0 = wm * 64 + mi * 16 + (l >> 2);
                int c0 = wn * 32 + nt * 8 + (l & 3) * 2;
                *(float2*)&sV[r0 * 66 + c0]       = make_float2(acc[mi][nt][0], acc[mi][nt][1]);
                *(float2*)&sV[(r0 + 8) * 66 + c0] = make_float2(acc[mi][nt][2], acc[mi][nt][3]);
            }
    }
    __syncthreads();
    if (isG) {
        const float* bvB = bv + (size_t)e * H_DIM;
        const float* bgB = bg + (size_t)e * H_DIM;
#pragma unroll
        for (int mi = 0; mi < 4; mi++)
#pragma unroll
            for (int nt = 0; nt < 4; nt++) {
                int r0 = wm * 64 + mi * 16 + (l >> 2);
                int c0 = wn * 32 + nt * 8 + (l & 3) * 2;
#pragma unroll
                for (int h8 = 0; h8 < 2; h8++) {
                    int row = r0 + h8 * 8;
                    int slot = rbase + row;
                    if (slot < rend) {
                        float2 vv = *(float2*)&sV[row * 66 + c0];
                        int gc = cbase + c0;
                        float o0 = 0.f, o1 = 0.f;
                        if (gc < H_DIM) {
                            float a = vv.x + bvB[gc];
                            float gg = acc[mi][nt][h8 * 2] + bgB[gc];
                            o0 = a / (1.f + __expf(-a)) * gg;
                        }
                        if (gc + 1 < H_DIM) {
                            float a = vv.y + bvB[gc + 1];
                            float gg = acc[mi][nt][h8 * 2 + 1] + bgB[gc + 1];
                            o1 = a / (1.f + __expf(-a)) * gg;
                        }
                        *(__half2*)&d_gh[(size_t)slot * HP2 + gc] = __floats2half2_rn(o0, o1);
                    }
                }
            }
    }
}

// ============ GEMM2: acc += w * (h @ Wo + bo), fp16 mma ============
// CTA 128 tok x 128 E-cols; warps 2(M) x 4(N), warp tile 64x32.
// stage: A 128x144B = 18432, B 64 k-rows x 272B = 17408.
__global__ void __launch_bounds__(256, 2) k_gemm2(const float* __restrict__ bo)
{
    int tile = blockIdx.x;
    if (tile >= g_ntiles) return;
    int e = g_tile_e[tile];
    int rbase = g_tile_r[tile];
    int rend  = g_off[e + 1];
    int cbase = blockIdx.y * 128;

    extern __shared__ __align__(16) char dsm[];
    uint32_t st0 = smem_u32(dsm);
    int t = threadIdx.x, w = t >> 5, l = t & 31;

    const __half* wop = d_woh + (size_t)e * KP2 * E_DIM + cbase;

    auto fill = [&](int c) {
        uint32_t sb = st0 + (c & 1) * ST2;
        int kb = c * KC;
#pragma unroll
        for (int i = 0; i < 4; i++) {          // A: 128 rows x 8 x 16B
            int ch = t + i * 256;
            int row = ch >> 3, cc = ch & 7;
            int slot = rbase + row; if (slot >= rend) slot = rend - 1;
            cpa16(sb + row * 144 + cc * 16, d_gh + (size_t)slot * HP2 + kb + cc * 8);
        }
#pragma unroll
        for (int i = 0; i < 4; i++) {          // B: 64 k-rows x 16 x 16B
            int ch = t + i * 256;
            int kr = ch >> 4, cc = ch & 15;
            cpa16(sb + 18432 + kr * 272 + cc * 16, wop + (size_t)(kb + kr) * E_DIM + cc * 8);
        }
    };

    float acc[4][4][4];
#pragma unroll
    for (int mi = 0; mi < 4; mi++)
#pragma unroll
        for (int nt = 0; nt < 4; nt++)
#pragma unroll
            for (int q = 0; q < 4; q++) acc[mi][nt][q] = 0.f;

    int wm = w & 1, wn = w >> 1;
    int g = l >> 3, lr = l & 7;
    uint32_t a_off = ((g & 1) * 8 + lr) * 144 + (g >> 1) * 16;
    uint32_t b_off = ((g & 1) * 8 + lr) * 272 + (g >> 1) * 16;

    fill(0); CPA_COMMIT();
    const int NC = KP2 / KC;  // 43
    for (int c = 0; c < NC; c++) {
        CPA_WAIT0();
        __syncthreads();
        if (c + 1 < NC) { fill(c + 1); CPA_COMMIT(); }
        uint32_t sb = st0 + (c & 1) * ST2;
        uint32_t aB = sb + wm * 64 * 144;
        uint32_t bB = sb + 18432 + wn * 64;
#pragma unroll
        for (int ks = 0; ks < 4; ks++) {
            uint32_t af[4][4], bf[2][4];
#pragma unroll
            for (int mi = 0; mi < 4; mi++)
                LDM4(af[mi], aB + mi * 16 * 144 + ks * 32 + a_off);
            LDM4T(bf[0], bB + ks * 16 * 272 + b_off);
            LDM4T(bf[1], bB + ks * 16 * 272 + 32 + b_off);
#pragma unroll
            for (int mi = 0; mi < 4; mi++) {
                mma16(acc[mi][0], af[mi], bf[0][0], bf[0][1]);
                mma16(acc[mi][1], af[mi], bf[0][2], bf[0][3]);
                mma16(acc[mi][2], af[mi], bf[1][0], bf[1][1]);
                mma16(acc[mi][3], af[mi], bf[1][2], bf[1][3]);
            }
        }
    }

    const float* boB = bo + (size_t)e * E_DIM;
#pragma unroll
    for (int mi = 0; mi < 4; mi++)
#pragma unroll
        for (int nt = 0; nt < 4; nt++) {
            int r0 = wm * 64 + mi * 16 + (l >> 2);
            int c0 = cbase + wn * 32 + nt * 8 + (l & 3) * 2;
#pragma unroll
            for (int h8 = 0; h8 < 2; h8++) {
                int slot = rbase + r0 + h8 * 8;
                if (slot < rend) {
                    int tok = g_tok[slot];
                    float ww = g_wt[slot];
                    float* dst = g_acc + (size_t)tok * E_DIM;
                    atomicAdd(&dst[c0],     ww * (acc[mi][nt][h8 * 2]     + boB[c0]));
                    atomicAdd(&dst[c0 + 1], ww * (acc[mi][nt][h8 * 2 + 1] + boB[c0 + 1]));
                }
            }
        }
}

// ---------------- LayerNorm ----------------
__global__ void k_ln(const float* __restrict__ lng, const float* __restrict__ lnb,
                     float* __restrict__ out)
{
    int n = blockIdx.x, tid = threadIdx.x;
    const float4* row = (const float4*)(g_acc + (size_t)n * E_DIM);
    float4 v = row[tid];
    float s  = v.x + v.y + v.z + v.w;
    float ss = v.x * v.x + v.y * v.y + v.z * v.z + v.w * v.w;
#pragma unroll
    for (int o = 16; o > 0; o >>= 1) {
        s  += __shfl_xor_sync(0xffffffffu, s,  o);
        ss += __shfl_xor_sync(0xffffffffu, ss, o);
    }
    __shared__ float sred[16];
    int w = tid >> 5, l = tid & 31;
    if (l == 0) { sred[w] = s; sred[8 + w] = ss; }
    __syncthreads();
    if (tid < 32) {
        float a = (tid < 8) ? sred[tid] : 0.f;
        float c = (tid < 8) ? sred[8 + tid] : 0.f;
#pragma unroll
        for (int o = 4; o > 0; o >>= 1) {
            a += __shfl_xor_sync(0xffffffffu, a, o);
            c += __shfl_xor_sync(0xffffffffu, c, o);
        }
        if (tid == 0) { sred[0] = a; sred[1] = c; }
    }
    __syncthreads();
    float mu  = sred[0] * (1.f / E_DIM);
    float var = sred[1] * (1.f / E_DIM) - mu * mu;
    float inv = rsqrtf(var + 1e-5f);
    float4 g4 = ((const float4*)lng)[tid];
    float4 b4 = ((const float4*)lnb)[tid];
    float4 o4;
    o4.x = (v.x - mu) * inv * g4.x + b4.x;
    o4.y = (v.y - mu) * inv * g4.y + b4.y;
    o4.z = (v.z - mu) * inv * g4.z + b4.z;
    o4.w = (v.w - mu) * inv * g4.w + b4.w;
    ((float4*)out)[(size_t)n * (E_DIM / 4) + tid] = o4;
}

// ---------------- launcher ----------------
extern "C" void kernel_launch(void* const* d_in, const int* in_sizes, int n_in,
                              void* d_out, int out_size)
{
    const float* x   = (const float*)d_in[0];
    const float* Wr  = (const float*)d_in[1];
    const float* Wv  = (const float*)d_in[2];
    const float* bv  = (const float*)d_in[3];
    const float* Wg  = (const float*)d_in[4];
    const float* bg  = (const float*)d_in[5];
    const float* Wo  = (const float*)d_in[6];
    const float* bo  = (const float*)d_in[7];
    const float* lng = (const float*)d_in[8];
    const float* lnb = (const float*)d_in[9];
    float* out = (float*)d_out;

    cudaFuncSetAttribute(k_gemm1, cudaFuncAttributeMaxDynamicSharedMemorySize, SM1);
    cudaFuncSetAttribute(k_gemm2, cudaFuncAttributeMaxDynamicSharedMemorySize, SM2);

    {
        size_t pvg = (size_t)NEXP * E_DIM * (HPH / 2);
        k_cvt_vg<<<(unsigned)((pvg + 255) / 256), 256>>>(Wv, Wg);
        size_t po = (size_t)NEXP * KP2 * (E_DIM / 2);
        k_cvt_o<<<(unsigned)((po + 255) / 256), 256>>>(Wo);
    }
    k_init<<<(N_TOK * E_DIM / 4) / 256, 256>>>(x);
    k_router<<<(N_TOK * 32) / 256, 256>>>(x, Wr);
    k_scatter_one<<<1, 1024>>>();

    dim3 g1(MAXT, 43);
    k_gemm1<<<g1, 256, SM1>>>(bv, bg);

    dim3 g2(MAXT, 8);
    k_gemm2<<<g2, 256, SM2>>>(bo);

    k_ln<<<N_TOK, 256>>>(lng, lnb, out);
}